// round 15
// baseline (speedup 1.0000x reference)
#include <cuda_runtime.h>
#include <cuda_fp16.h>
#include <stdint.h>
#include <math.h>

#define NT    65536
#define NSPEC 4
#define DIN   256
#define DHID  1024
#define DOUT  256
#define MT    192            // max m-tiles per species (24576 rows capacity)

// ---------------------------------------------------------------------------
// Device-global scratch (allocation-free rule).
// ---------------------------------------------------------------------------
__device__ int g_cnt[NSPEC];
__device__ int g_or_odd;
__device__ int g_idx[NSPEC * NT];
__device__ __half g_x16[(size_t)NT * DIN];
__device__ __half g_H16[(size_t)NT * DHID];
__device__ __half g_w1[(size_t)NSPEC * DHID * DIN];   // [s][n][k] fp16
__device__ __half g_w2[(size_t)NSPEC * DOUT * DHID];

// ---------------------------------------------------------------------------
// Helpers
// ---------------------------------------------------------------------------
__device__ __forceinline__ uint32_t s2u(const void* p) {
    uint32_t a;
    asm("{ .reg .u64 t; cvta.to.shared.u64 t, %1; cvt.u32.u64 %0, t; }" : "=r"(a) : "l"(p));
    return a;
}
__device__ __forceinline__ uint32_t swz(uint32_t o) { return o ^ ((o >> 3) & 0x70u); }

#define CP_COMMIT() asm volatile("cp.async.commit_group;" ::: "memory")
template<int N> __device__ __forceinline__ void cp_wait() {
    asm volatile("cp.async.wait_group %0;" :: "n"(N) : "memory");
}
__device__ __forceinline__ void cp16z(uint32_t dst, const void* src, unsigned sz) {
    asm volatile("cp.async.cg.shared.global [%0], [%1], 16, %2;"
                 :: "r"(dst), "l"(src), "r"(sz) : "memory");
}

#define LDM4(r, a) \
    asm volatile("ldmatrix.sync.aligned.m8n8.x4.shared.b16 {%0,%1,%2,%3}, [%4];" \
                 : "=r"((r)[0]), "=r"((r)[1]), "=r"((r)[2]), "=r"((r)[3]) : "r"(a))

#define MMA(c, a, b) \
    asm volatile("mma.sync.aligned.m16n8k16.row.col.f32.f16.f16.f32 " \
                 "{%0,%1,%2,%3},{%4,%5,%6,%7},{%8,%9},{%0,%1,%2,%3};" \
                 : "+f"((c)[0]), "+f"((c)[1]), "+f"((c)[2]), "+f"((c)[3]) \
                 : "r"((a)[0]), "r"((a)[1]), "r"((a)[2]), "r"((a)[3]), \
                   "r"((b)[0]), "r"((b)[1]))

// ---------------------------------------------------------------------------
// conv_x: fp32 -> fp16 (pure streaming; main stream).
// ---------------------------------------------------------------------------
__global__ void conv_x(const float* __restrict__ x) {
    size_t i = ((size_t)blockIdx.x * 256 + threadIdx.x) * 4;
    float4 v = *(const float4*)(x + i);
    uint2 p;
    p.x = (uint32_t)__half_as_ushort(__float2half_rn(v.x))
        | ((uint32_t)__half_as_ushort(__float2half_rn(v.y)) << 16);
    p.y = (uint32_t)__half_as_ushort(__float2half_rn(v.z))
        | ((uint32_t)__half_as_ushort(__float2half_rn(v.w)) << 16);
    ((uint2*)g_x16)[i / 4] = p;
}

// ---------------------------------------------------------------------------
// Probe + counter reset (single block). Species dtype is ambiguous (JAX
// x64-off silently emits int32): int64 with values 0..3 has every odd 32-bit
// word zero; random int32 0..3 fails w.p. 1 - 4^-2048.
// ---------------------------------------------------------------------------
__global__ void k_probe(const int* __restrict__ w) {
    __shared__ int red[8];
    if (threadIdx.x < NSPEC) g_cnt[threadIdx.x] = 0;
    int v = 0;
#pragma unroll
    for (int j = 0; j < 8; j++)
        v |= w[2 * (threadIdx.x + j * 256) + 1];
    for (int o = 16; o > 0; o >>= 1) v |= __shfl_xor_sync(0xffffffffu, v, o);
    if ((threadIdx.x & 31) == 0) red[threadIdx.x >> 5] = v;
    __syncthreads();
    if (threadIdx.x == 0) {
        int r = 0;
#pragma unroll
        for (int j = 0; j < 8; j++) r |= red[j];
        g_or_odd = r;
    }
}

// ---------------------------------------------------------------------------
// Block-aggregated scatter: warp ballots -> per-warp smem histogram ->
// warp-scan -> 4 global atomics per block (256 total).
// ---------------------------------------------------------------------------
__global__ void __launch_bounds__(1024) k_scatter(const int* __restrict__ w) {
    __shared__ int wcnt[32][NSPEC];
    __shared__ int sbase[NSPEC];
    const int tid = threadIdx.x, wid = tid >> 5, lane = tid & 31;
    const int i = blockIdx.x * 1024 + tid;
    bool is64 = (g_or_odd == 0);
    int s = is64 ? w[2 * i] : w[i];
    int rank = 0;
#pragma unroll
    for (int t = 0; t < NSPEC; t++) {
        unsigned m = __ballot_sync(0xffffffffu, s == t);
        if (lane == 0) wcnt[wid][t] = __popc(m);
        if (s == t) rank = __popc(m & ((1u << lane) - 1u));
    }
    __syncthreads();
    if (wid < NSPEC) {                 // warp `wid` scans species `wid`
        int c = wcnt[lane][wid];
        int incl = c;
#pragma unroll
        for (int o = 1; o < 32; o <<= 1) {
            int n = __shfl_up_sync(0xffffffffu, incl, o);
            if (lane >= o) incl += n;
        }
        wcnt[lane][wid] = incl - c;    // exclusive prefix
        if (lane == 31) sbase[wid] = atomicAdd(&g_cnt[wid], incl);
    }
    __syncthreads();
    if ((unsigned)s < NSPEC)
        g_idx[s * NT + sbase[s] + wcnt[wid][s] + rank] = i;
}

// ---------------------------------------------------------------------------
// Merged weight transpose+convert: W1 blocks [0,1024), W2 blocks [1024,2048)
// ---------------------------------------------------------------------------
__global__ void conv_w_all(const float* __restrict__ W1, const float* __restrict__ W2) {
    __shared__ float sm[32][33];
    int id = blockIdx.x;
    const float* W; __half* T; int KD, ND, k0, n0, s;
    if (id < 1024) {
        W = W1; T = g_w1; KD = DIN; ND = DHID;
        k0 = (id & 7) * 32; n0 = ((id >> 3) & 31) * 32; s = id >> 8;
    } else {
        int j = id - 1024;
        W = W2; T = g_w2; KD = DHID; ND = DOUT;
        k0 = (j & 31) * 32; n0 = ((j >> 5) & 7) * 32; s = j >> 8;
    }
    int tx = threadIdx.x, ty = threadIdx.y;   // (32, 8)
    const float* Wp = W + (size_t)s * KD * ND;
#pragma unroll
    for (int j = 0; j < 4; j++)
        sm[ty + j * 8][tx] = Wp[(size_t)(k0 + ty + j * 8) * ND + n0 + tx];
    __syncthreads();
#pragma unroll
    for (int j = 0; j < 4; j++) {
        int n = ty + j * 8;
        T[((size_t)s * ND + n0 + n) * KD + k0 + tx] = __float2half_rn(sm[tx][n]);
    }
}

// ---------------------------------------------------------------------------
// mma.sync fp16 GEMM over ONE species bucket (species passed as argument so
// per-species sub-launches can pipeline GEMM1(s) -> GEMM2(s) across streams).
//   Block 128x128, K chunks of 64. 8 warps: warp tile 64x32.
//   3-stage cp.async pipeline, one __syncthreads per chunk, occupancy 2.
// Dynamic SMEM: 3 stages x 32KB (A 16K | B 16K), SW128-swizzled 128B rows.
// ---------------------------------------------------------------------------
#define GEMM_SMEM 98304

template<int KT, int NDIM, bool GATHER_A, bool SCATTER_OUT, bool DO_SILU>
__global__ void __launch_bounds__(256, 2)
moe_gemm(const __half* __restrict__ A, const __half* __restrict__ B,
         const float* __restrict__ bias,
         __half* __restrict__ O16, float* __restrict__ Of, int s)
{
    constexpr int NC = KT / 64;
    extern __shared__ char dyn[];
    __shared__ int   tok[128];
    __shared__ float bsm[128];

    const int tid = threadIdx.x, wid = tid >> 5, lane = tid & 31;
    const int cnt = g_cnt[s];
    const int m0  = blockIdx.x * 128;
    if (m0 >= cnt) return;
    const int n0    = blockIdx.y * 128;
    const int valid = min(128, cnt - m0);
    int off = 0;
#pragma unroll
    for (int t = 0; t < NSPEC; t++) if (t < s) off += g_cnt[t];
    const uint32_t sbase = s2u(dyn);

    for (int i = tid; i < 128; i += 256)
        tok[i] = (i < valid) ? g_idx[s * NT + m0 + i] : -1;
    if (tid < 128) bsm[tid] = bias[(size_t)s * NDIM + n0 + tid];
    __syncthreads();

    auto issue = [&](int c) {
        const int k0 = c * 64;
        const uint32_t bb = sbase + (uint32_t)(c % 3) * 32768u;
#pragma unroll
        for (int i = 0; i < 4; i++) {          // A: 128 rows x 8 units
            int t = tid + i * 256;
            int row = t >> 3, u = t & 7;
            int gr;
            if (GATHER_A) gr = tok[row];
            else          gr = (row < valid) ? (off + m0 + row) : -1;
            const __half* src = A + (size_t)max(gr, 0) * KT + k0 + u * 8;
            cp16z(bb + swz((uint32_t)row * 128u + u * 16u), src, (gr >= 0) ? 16u : 0u);
        }
#pragma unroll
        for (int i = 0; i < 4; i++) {          // B: 128 rows x 8 units
            int t = tid + i * 256;
            int row = t >> 3, u = t & 7;
            const __half* src = B + ((size_t)s * NDIM + n0 + row) * KT + k0 + u * 8;
            cp16z(bb + 16384u + swz((uint32_t)row * 128u + u * 16u), src, 16u);
        }
        CP_COMMIT();
    };

    float acc[4][4][4];
#pragma unroll
    for (int a = 0; a < 4; a++)
#pragma unroll
        for (int b = 0; b < 4; b++)
#pragma unroll
            for (int q = 0; q < 4; q++) acc[a][b][q] = 0.f;

    const int wm = wid & 1;
    const int wn = wid >> 1;
    const int ra = (lane & 7) + ((lane >> 3) & 1) * 8;
    const int ca = ((lane >> 4) & 1) * 8;
    const int rb = (lane & 7) + ((lane >> 4) & 1) * 8;
    const int cb = ((lane >> 3) & 1) * 8;

    issue(0);
    if (NC > 1) issue(1);
#pragma unroll 1
    for (int c = 0; c < NC; c++) {
        if (c + 1 < NC) cp_wait<1>();
        else            cp_wait<0>();
        __syncthreads();
        if (c + 2 < NC) issue(c + 2);
        const uint32_t bb = sbase + (uint32_t)(c % 3) * 32768u;
#pragma unroll
        for (int ks = 0; ks < 4; ks++) {
            uint32_t af[4][4], bf[2][4];
#pragma unroll
            for (int mt = 0; mt < 4; mt++) {
                uint32_t o = (uint32_t)((wm * 64 + mt * 16 + ra) * 128
                                        + (ks * 16 + ca) * 2);
                LDM4(af[mt], bb + swz(o));
            }
#pragma unroll
            for (int np = 0; np < 2; np++) {
                uint32_t o = (uint32_t)((wn * 32 + np * 16 + rb) * 128
                                        + (ks * 16 + cb) * 2);
                LDM4(bf[np], bb + 16384u + swz(o));
            }
#pragma unroll
            for (int mt = 0; mt < 4; mt++)
#pragma unroll
                for (int nt = 0; nt < 4; nt++)
                    MMA(acc[mt][nt], af[mt], &bf[nt >> 1][(nt & 1) * 2]);
        }
    }

    const int gid = lane >> 2, tig = lane & 3;
#pragma unroll
    for (int mt = 0; mt < 4; mt++)
#pragma unroll
        for (int half = 0; half < 2; half++) {
            int lrow = wm * 64 + mt * 16 + gid + half * 8;
            if (lrow >= valid) continue;
            int orow = SCATTER_OUT ? tok[lrow] : (off + m0 + lrow);
#pragma unroll
            for (int nt = 0; nt < 4; nt++) {
                int col = wn * 32 + nt * 8 + tig * 2;
                float v0 = acc[mt][nt][half * 2 + 0] + bsm[col];
                float v1 = acc[mt][nt][half * 2 + 1] + bsm[col + 1];
                if (DO_SILU) {
                    v0 = v0 / (1.f + __expf(-v0));
                    v1 = v1 / (1.f + __expf(-v1));
                    uint32_t p = (uint32_t)__half_as_ushort(__float2half_rn(v0))
                               | ((uint32_t)__half_as_ushort(__float2half_rn(v1)) << 16);
                    *(uint32_t*)(O16 + (size_t)orow * NDIM + n0 + col) = p;
                } else {
                    float2 v = make_float2(v0, v1);
                    *(float2*)(Of + (size_t)orow * NDIM + n0 + col) = v;
                }
            }
        }
}

#define GEMM1_LAUNCH(stream, sp) \
    moe_gemm<DIN, DHID, true, false, true> \
        <<<dim3(MT, DHID / 128), 256, GEMM_SMEM, stream>>>(x16, w1, b1, H16, nullptr, sp)
#define GEMM2_LAUNCH(stream, sp) \
    moe_gemm<DHID, DOUT, false, true, false> \
        <<<dim3(MT, DOUT / 128), 256, GEMM_SMEM, stream>>>(H16, w2, b2, nullptr, out, sp)

// ---------------------------------------------------------------------------
// Launch. ONLY the two side streams that already passed the allocation
// check (round 13) — no new streams. Three GEMM pipelines:
//   s1:   conv_w -> G1(1) -> G2(1)
//   s2:   probe -> scatter -> G1(2) -> G2(2)
//   main: conv_x -> G1(0) -> G1(3) -> G2(0) -> G2(3)
// ---------------------------------------------------------------------------
extern "C" void kernel_launch(void* const* d_in, const int* in_sizes, int n_in,
                              void* d_out, int out_size)
{
    const float* x   = (const float*)d_in[0];
    const int*   spw = (const int*)d_in[1];
    const float* W1  = (const float*)d_in[2];
    const float* b1  = (const float*)d_in[3];
    const float* W2  = (const float*)d_in[4];
    const float* b2  = (const float*)d_in[5];
    float*       out = (float*)d_out;

    __half *x16, *H16, *w1, *w2;
    cudaGetSymbolAddress((void**)&x16, g_x16);
    cudaGetSymbolAddress((void**)&H16, g_H16);
    cudaGetSymbolAddress((void**)&w1,  g_w1);
    cudaGetSymbolAddress((void**)&w2,  g_w2);

    static cudaStream_t s1 = nullptr, s2 = nullptr;
    static cudaEvent_t  evF = nullptr, evJ1 = nullptr, evJ2 = nullptr,
                        evX = nullptr, evD1 = nullptr, evD2 = nullptr;
    if (!s1) {
        cudaStreamCreateWithFlags(&s1, cudaStreamNonBlocking);
        cudaStreamCreateWithFlags(&s2, cudaStreamNonBlocking);
        cudaEventCreateWithFlags(&evF,  cudaEventDisableTiming);
        cudaEventCreateWithFlags(&evJ1, cudaEventDisableTiming);
        cudaEventCreateWithFlags(&evJ2, cudaEventDisableTiming);
        cudaEventCreateWithFlags(&evX,  cudaEventDisableTiming);
        cudaEventCreateWithFlags(&evD1, cudaEventDisableTiming);
        cudaEventCreateWithFlags(&evD2, cudaEventDisableTiming);
        cudaFuncSetAttribute(moe_gemm<DIN,  DHID, true,  false, true>,
                             cudaFuncAttributeMaxDynamicSharedMemorySize, GEMM_SMEM);
        cudaFuncSetAttribute(moe_gemm<DHID, DOUT, false, true,  false>,
                             cudaFuncAttributeMaxDynamicSharedMemorySize, GEMM_SMEM);
    }

    // Fork the three independent pre-phase chains.
    cudaEventRecord(evF, 0);
    cudaStreamWaitEvent(s1, evF, 0);
    cudaStreamWaitEvent(s2, evF, 0);

    conv_w_all<<<2048, dim3(32, 8), 0, s1>>>(W1, W2);
    cudaEventRecord(evJ1, s1);

    k_probe  <<<1, 256, 0, s2>>>(spw);     // + counter resets
    k_scatter<<<64, 1024, 0, s2>>>(spw);
    cudaEventRecord(evJ2, s2);

    conv_x<<<NT * DIN / 4 / 256, 256>>>(x);   // main stream
    cudaEventRecord(evX, 0);

    // s1 pipeline: species 1 (conv_w in-stream; needs x16 + buckets).
    cudaStreamWaitEvent(s1, evX,  0);
    cudaStreamWaitEvent(s1, evJ2, 0);
    GEMM1_LAUNCH(s1, 1);
    GEMM2_LAUNCH(s1, 1);
    cudaEventRecord(evD1, s1);

    // s2 pipeline: species 2 (buckets in-stream; needs x16 + weights).
    cudaStreamWaitEvent(s2, evX,  0);
    cudaStreamWaitEvent(s2, evJ1, 0);
    GEMM1_LAUNCH(s2, 2);
    GEMM2_LAUNCH(s2, 2);
    cudaEventRecord(evD2, s2);

    // Main pipeline: species 0 and 3 (conv_x in-stream; needs weights+buckets).
    cudaStreamWaitEvent(0, evJ1, 0);
    cudaStreamWaitEvent(0, evJ2, 0);
    GEMM1_LAUNCH(0, 0);
    GEMM1_LAUNCH(0, 3);
    GEMM2_LAUNCH(0, 0);
    GEMM2_LAUNCH(0, 3);

    // Join side pipelines on the main stream.
    cudaStreamWaitEvent(0, evD1, 0);
    cudaStreamWaitEvent(0, evD2, 0);
}

// round 16
// speedup vs baseline: 1.0002x; 1.0002x over previous
#include <cuda_runtime.h>
#include <cuda_fp16.h>
#include <stdint.h>
#include <math.h>

#define NT    65536
#define NSPEC 4
#define DIN   256
#define DHID  1024
#define DOUT  256
#define MT    192            // max m-tiles per species (24576 rows capacity)

// ---------------------------------------------------------------------------
// Device-global scratch (allocation-free rule).
// ---------------------------------------------------------------------------
__device__ int g_cnt[NSPEC];
__device__ int g_or_odd;
__device__ int g_idx[NSPEC * NT];
__device__ __half g_x16[(size_t)NT * DIN];
__device__ __half g_H16[(size_t)NT * DHID];
__device__ __half g_w1[(size_t)NSPEC * DHID * DIN];   // [s][n][k] fp16
__device__ __half g_w2[(size_t)NSPEC * DOUT * DHID];

// ---------------------------------------------------------------------------
// Helpers
// ---------------------------------------------------------------------------
__device__ __forceinline__ uint32_t s2u(const void* p) {
    uint32_t a;
    asm("{ .reg .u64 t; cvta.to.shared.u64 t, %1; cvt.u32.u64 %0, t; }" : "=r"(a) : "l"(p));
    return a;
}
__device__ __forceinline__ uint32_t swz(uint32_t o) { return o ^ ((o >> 3) & 0x70u); }

#define CP_COMMIT() asm volatile("cp.async.commit_group;" ::: "memory")
template<int N> __device__ __forceinline__ void cp_wait() {
    asm volatile("cp.async.wait_group %0;" :: "n"(N) : "memory");
}
__device__ __forceinline__ void cp16z(uint32_t dst, const void* src, unsigned sz) {
    asm volatile("cp.async.cg.shared.global [%0], [%1], 16, %2;"
                 :: "r"(dst), "l"(src), "r"(sz) : "memory");
}

#define LDM4(r, a) \
    asm volatile("ldmatrix.sync.aligned.m8n8.x4.shared.b16 {%0,%1,%2,%3}, [%4];" \
                 : "=r"((r)[0]), "=r"((r)[1]), "=r"((r)[2]), "=r"((r)[3]) : "r"(a))

#define MMA(c, a, b) \
    asm volatile("mma.sync.aligned.m16n8k16.row.col.f32.f16.f16.f32 " \
                 "{%0,%1,%2,%3},{%4,%5,%6,%7},{%8,%9},{%0,%1,%2,%3};" \
                 : "+f"((c)[0]), "+f"((c)[1]), "+f"((c)[2]), "+f"((c)[3]) \
                 : "r"((a)[0]), "r"((a)[1]), "r"((a)[2]), "r"((a)[3]), \
                   "r"((b)[0]), "r"((b)[1]))

// ---------------------------------------------------------------------------
// conv_x: fp32 -> fp16 (pure streaming; main stream).
// ---------------------------------------------------------------------------
__global__ void conv_x(const float* __restrict__ x) {
    size_t i = ((size_t)blockIdx.x * 256 + threadIdx.x) * 4;
    float4 v = *(const float4*)(x + i);
    uint2 p;
    p.x = (uint32_t)__half_as_ushort(__float2half_rn(v.x))
        | ((uint32_t)__half_as_ushort(__float2half_rn(v.y)) << 16);
    p.y = (uint32_t)__half_as_ushort(__float2half_rn(v.z))
        | ((uint32_t)__half_as_ushort(__float2half_rn(v.w)) << 16);
    ((uint2*)g_x16)[i / 4] = p;
}

// ---------------------------------------------------------------------------
// Probe + counter reset (single block). Species dtype is ambiguous (JAX
// x64-off silently emits int32): int64 with values 0..3 has every odd 32-bit
// word zero; random int32 0..3 fails w.p. 1 - 4^-2048.
// ---------------------------------------------------------------------------
__global__ void k_probe(const int* __restrict__ w) {
    __shared__ int red[8];
    if (threadIdx.x < NSPEC) g_cnt[threadIdx.x] = 0;
    int v = 0;
#pragma unroll
    for (int j = 0; j < 8; j++)
        v |= w[2 * (threadIdx.x + j * 256) + 1];
    for (int o = 16; o > 0; o >>= 1) v |= __shfl_xor_sync(0xffffffffu, v, o);
    if ((threadIdx.x & 31) == 0) red[threadIdx.x >> 5] = v;
    __syncthreads();
    if (threadIdx.x == 0) {
        int r = 0;
#pragma unroll
        for (int j = 0; j < 8; j++) r |= red[j];
        g_or_odd = r;
    }
}

// ---------------------------------------------------------------------------
// Block-aggregated scatter: warp ballots -> per-warp smem histogram ->
// warp-scan -> 4 global atomics per block (256 total).
// ---------------------------------------------------------------------------
__global__ void __launch_bounds__(1024) k_scatter(const int* __restrict__ w) {
    __shared__ int wcnt[32][NSPEC];
    __shared__ int sbase[NSPEC];
    const int tid = threadIdx.x, wid = tid >> 5, lane = tid & 31;
    const int i = blockIdx.x * 1024 + tid;
    bool is64 = (g_or_odd == 0);
    int s = is64 ? w[2 * i] : w[i];
    int rank = 0;
#pragma unroll
    for (int t = 0; t < NSPEC; t++) {
        unsigned m = __ballot_sync(0xffffffffu, s == t);
        if (lane == 0) wcnt[wid][t] = __popc(m);
        if (s == t) rank = __popc(m & ((1u << lane) - 1u));
    }
    __syncthreads();
    if (wid < NSPEC) {                 // warp `wid` scans species `wid`
        int c = wcnt[lane][wid];
        int incl = c;
#pragma unroll
        for (int o = 1; o < 32; o <<= 1) {
            int n = __shfl_up_sync(0xffffffffu, incl, o);
            if (lane >= o) incl += n;
        }
        wcnt[lane][wid] = incl - c;    // exclusive prefix
        if (lane == 31) sbase[wid] = atomicAdd(&g_cnt[wid], incl);
    }
    __syncthreads();
    if ((unsigned)s < NSPEC)
        g_idx[s * NT + sbase[s] + wcnt[wid][s] + rank] = i;
}

// ---------------------------------------------------------------------------
// Merged weight transpose+convert: W1 blocks [0,1024), W2 blocks [1024,2048)
// ---------------------------------------------------------------------------
__global__ void conv_w_all(const float* __restrict__ W1, const float* __restrict__ W2) {
    __shared__ float sm[32][33];
    int id = blockIdx.x;
    const float* W; __half* T; int KD, ND, k0, n0, s;
    if (id < 1024) {
        W = W1; T = g_w1; KD = DIN; ND = DHID;
        k0 = (id & 7) * 32; n0 = ((id >> 3) & 31) * 32; s = id >> 8;
    } else {
        int j = id - 1024;
        W = W2; T = g_w2; KD = DHID; ND = DOUT;
        k0 = (j & 31) * 32; n0 = ((j >> 5) & 7) * 32; s = j >> 8;
    }
    int tx = threadIdx.x, ty = threadIdx.y;   // (32, 8)
    const float* Wp = W + (size_t)s * KD * ND;
#pragma unroll
    for (int j = 0; j < 4; j++)
        sm[ty + j * 8][tx] = Wp[(size_t)(k0 + ty + j * 8) * ND + n0 + tx];
    __syncthreads();
#pragma unroll
    for (int j = 0; j < 4; j++) {
        int n = ty + j * 8;
        T[((size_t)s * ND + n0 + n) * KD + k0 + tx] = __float2half_rn(sm[tx][n]);
    }
}

// ---------------------------------------------------------------------------
// mma.sync fp16 GEMM over ONE species bucket (species passed as argument so
// per-species sub-launches can pipeline GEMM1(s) -> GEMM2(s) across streams).
//   Block 128x128, K chunks of 64. 8 warps: warp tile 64x32.
//   3-stage cp.async pipeline, one __syncthreads per chunk, occupancy 2.
// Dynamic SMEM: 3 stages x 32KB (A 16K | B 16K), SW128-swizzled 128B rows.
// ---------------------------------------------------------------------------
#define GEMM_SMEM 98304

template<int KT, int NDIM, bool GATHER_A, bool SCATTER_OUT, bool DO_SILU>
__global__ void __launch_bounds__(256, 2)
moe_gemm(const __half* __restrict__ A, const __half* __restrict__ B,
         const float* __restrict__ bias,
         __half* __restrict__ O16, float* __restrict__ Of, int s)
{
    constexpr int NC = KT / 64;
    extern __shared__ char dyn[];
    __shared__ int   tok[128];
    __shared__ float bsm[128];

    const int tid = threadIdx.x, wid = tid >> 5, lane = tid & 31;
    const int cnt = g_cnt[s];
    const int m0  = blockIdx.x * 128;
    if (m0 >= cnt) return;
    const int n0    = blockIdx.y * 128;
    const int valid = min(128, cnt - m0);
    int off = 0;
#pragma unroll
    for (int t = 0; t < NSPEC; t++) if (t < s) off += g_cnt[t];
    const uint32_t sbase = s2u(dyn);

    for (int i = tid; i < 128; i += 256)
        tok[i] = (i < valid) ? g_idx[s * NT + m0 + i] : -1;
    if (tid < 128) bsm[tid] = bias[(size_t)s * NDIM + n0 + tid];
    __syncthreads();

    auto issue = [&](int c) {
        const int k0 = c * 64;
        const uint32_t bb = sbase + (uint32_t)(c % 3) * 32768u;
#pragma unroll
        for (int i = 0; i < 4; i++) {          // A: 128 rows x 8 units
            int t = tid + i * 256;
            int row = t >> 3, u = t & 7;
            int gr;
            if (GATHER_A) gr = tok[row];
            else          gr = (row < valid) ? (off + m0 + row) : -1;
            const __half* src = A + (size_t)max(gr, 0) * KT + k0 + u * 8;
            cp16z(bb + swz((uint32_t)row * 128u + u * 16u), src, (gr >= 0) ? 16u : 0u);
        }
#pragma unroll
        for (int i = 0; i < 4; i++) {          // B: 128 rows x 8 units
            int t = tid + i * 256;
            int row = t >> 3, u = t & 7;
            const __half* src = B + ((size_t)s * NDIM + n0 + row) * KT + k0 + u * 8;
            cp16z(bb + 16384u + swz((uint32_t)row * 128u + u * 16u), src, 16u);
        }
        CP_COMMIT();
    };

    float acc[4][4][4];
#pragma unroll
    for (int a = 0; a < 4; a++)
#pragma unroll
        for (int b = 0; b < 4; b++)
#pragma unroll
            for (int q = 0; q < 4; q++) acc[a][b][q] = 0.f;

    const int wm = wid & 1;
    const int wn = wid >> 1;
    const int ra = (lane & 7) + ((lane >> 3) & 1) * 8;
    const int ca = ((lane >> 4) & 1) * 8;
    const int rb = (lane & 7) + ((lane >> 4) & 1) * 8;
    const int cb = ((lane >> 3) & 1) * 8;

    issue(0);
    if (NC > 1) issue(1);
#pragma unroll 1
    for (int c = 0; c < NC; c++) {
        if (c + 1 < NC) cp_wait<1>();
        else            cp_wait<0>();
        __syncthreads();
        if (c + 2 < NC) issue(c + 2);
        const uint32_t bb = sbase + (uint32_t)(c % 3) * 32768u;
#pragma unroll
        for (int ks = 0; ks < 4; ks++) {
            uint32_t af[4][4], bf[2][4];
#pragma unroll
            for (int mt = 0; mt < 4; mt++) {
                uint32_t o = (uint32_t)((wm * 64 + mt * 16 + ra) * 128
                                        + (ks * 16 + ca) * 2);
                LDM4(af[mt], bb + swz(o));
            }
#pragma unroll
            for (int np = 0; np < 2; np++) {
                uint32_t o = (uint32_t)((wn * 32 + np * 16 + rb) * 128
                                        + (ks * 16 + cb) * 2);
                LDM4(bf[np], bb + 16384u + swz(o));
            }
#pragma unroll
            for (int mt = 0; mt < 4; mt++)
#pragma unroll
                for (int nt = 0; nt < 4; nt++)
                    MMA(acc[mt][nt], af[mt], &bf[nt >> 1][(nt & 1) * 2]);
        }
    }

    const int gid = lane >> 2, tig = lane & 3;
#pragma unroll
    for (int mt = 0; mt < 4; mt++)
#pragma unroll
        for (int half = 0; half < 2; half++) {
            int lrow = wm * 64 + mt * 16 + gid + half * 8;
            if (lrow >= valid) continue;
            int orow = SCATTER_OUT ? tok[lrow] : (off + m0 + lrow);
#pragma unroll
            for (int nt = 0; nt < 4; nt++) {
                int col = wn * 32 + nt * 8 + tig * 2;
                float v0 = acc[mt][nt][half * 2 + 0] + bsm[col];
                float v1 = acc[mt][nt][half * 2 + 1] + bsm[col + 1];
                if (DO_SILU) {
                    v0 = v0 / (1.f + __expf(-v0));
                    v1 = v1 / (1.f + __expf(-v1));
                    uint32_t p = (uint32_t)__half_as_ushort(__float2half_rn(v0))
                               | ((uint32_t)__half_as_ushort(__float2half_rn(v1)) << 16);
                    *(uint32_t*)(O16 + (size_t)orow * NDIM + n0 + col) = p;
                } else {
                    float2 v = make_float2(v0, v1);
                    *(float2*)(Of + (size_t)orow * NDIM + n0 + col) = v;
                }
            }
        }
}

#define GEMM1_LAUNCH(stream, sp) \
    moe_gemm<DIN, DHID, true, false, true> \
        <<<dim3(MT, DHID / 128), 256, GEMM_SMEM, stream>>>(x16, w1, b1, H16, nullptr, sp)
#define GEMM2_LAUNCH(stream, sp) \
    moe_gemm<DHID, DOUT, false, true, false> \
        <<<dim3(MT, DOUT / 128), 256, GEMM_SMEM, stream>>>(H16, w2, b2, nullptr, out, sp)

// ---------------------------------------------------------------------------
// Launch. ONLY the two side streams that already passed the allocation
// check (round 13) — no new streams. Three GEMM pipelines:
//   s1:   conv_w -> G1(1) -> G2(1)
//   s2:   probe -> scatter -> G1(2) -> G2(2)
//   main: conv_x -> G1(0) -> G1(3) -> G2(0) -> G2(3)
// ---------------------------------------------------------------------------
extern "C" void kernel_launch(void* const* d_in, const int* in_sizes, int n_in,
                              void* d_out, int out_size)
{
    const float* x   = (const float*)d_in[0];
    const int*   spw = (const int*)d_in[1];
    const float* W1  = (const float*)d_in[2];
    const float* b1  = (const float*)d_in[3];
    const float* W2  = (const float*)d_in[4];
    const float* b2  = (const float*)d_in[5];
    float*       out = (float*)d_out;

    __half *x16, *H16, *w1, *w2;
    cudaGetSymbolAddress((void**)&x16, g_x16);
    cudaGetSymbolAddress((void**)&H16, g_H16);
    cudaGetSymbolAddress((void**)&w1,  g_w1);
    cudaGetSymbolAddress((void**)&w2,  g_w2);

    static cudaStream_t s1 = nullptr, s2 = nullptr;
    static cudaEvent_t  evF = nullptr, evJ1 = nullptr, evJ2 = nullptr,
                        evX = nullptr, evD1 = nullptr, evD2 = nullptr;
    if (!s1) {
        cudaStreamCreateWithFlags(&s1, cudaStreamNonBlocking);
        cudaStreamCreateWithFlags(&s2, cudaStreamNonBlocking);
        cudaEventCreateWithFlags(&evF,  cudaEventDisableTiming);
        cudaEventCreateWithFlags(&evJ1, cudaEventDisableTiming);
        cudaEventCreateWithFlags(&evJ2, cudaEventDisableTiming);
        cudaEventCreateWithFlags(&evX,  cudaEventDisableTiming);
        cudaEventCreateWithFlags(&evD1, cudaEventDisableTiming);
        cudaEventCreateWithFlags(&evD2, cudaEventDisableTiming);
        cudaFuncSetAttribute(moe_gemm<DIN,  DHID, true,  false, true>,
                             cudaFuncAttributeMaxDynamicSharedMemorySize, GEMM_SMEM);
        cudaFuncSetAttribute(moe_gemm<DHID, DOUT, false, true,  false>,
                             cudaFuncAttributeMaxDynamicSharedMemorySize, GEMM_SMEM);
    }

    // Fork the three independent pre-phase chains.
    cudaEventRecord(evF, 0);
    cudaStreamWaitEvent(s1, evF, 0);
    cudaStreamWaitEvent(s2, evF, 0);

    conv_w_all<<<2048, dim3(32, 8), 0, s1>>>(W1, W2);
    cudaEventRecord(evJ1, s1);

    k_probe  <<<1, 256, 0, s2>>>(spw);     // + counter resets
    k_scatter<<<64, 1024, 0, s2>>>(spw);
    cudaEventRecord(evJ2, s2);

    conv_x<<<NT * DIN / 4 / 256, 256>>>(x);   // main stream
    cudaEventRecord(evX, 0);

    // s1 pipeline: species 1 (conv_w in-stream; needs x16 + buckets).
    cudaStreamWaitEvent(s1, evX,  0);
    cudaStreamWaitEvent(s1, evJ2, 0);
    GEMM1_LAUNCH(s1, 1);
    GEMM2_LAUNCH(s1, 1);
    cudaEventRecord(evD1, s1);

    // s2 pipeline: species 2 (buckets in-stream; needs x16 + weights).
    cudaStreamWaitEvent(s2, evX,  0);
    cudaStreamWaitEvent(s2, evJ1, 0);
    GEMM1_LAUNCH(s2, 2);
    GEMM2_LAUNCH(s2, 2);
    cudaEventRecord(evD2, s2);

    // Main pipeline: species 0 and 3 (conv_x in-stream; needs weights+buckets).
    cudaStreamWaitEvent(0, evJ1, 0);
    cudaStreamWaitEvent(0, evJ2, 0);
    GEMM1_LAUNCH(0, 0);
    GEMM1_LAUNCH(0, 3);
    GEMM2_LAUNCH(0, 0);
    GEMM2_LAUNCH(0, 3);

    // Join side pipelines on the main stream.
    cudaStreamWaitEvent(0, evD1, 0);
    cudaStreamWaitEvent(0, evD2, 0);
}

// round 17
// speedup vs baseline: 1.0542x; 1.0540x over previous
#include <cuda_runtime.h>
#include <cuda_fp16.h>
#include <stdint.h>
#include <math.h>

#define NT    65536
#define NSPEC 4
#define DIN   256
#define DHID  1024
#define DOUT  256
#define MT    192            // max m-tiles per species (24576 rows capacity)

// ---------------------------------------------------------------------------
// Device-global scratch (allocation-free rule).
// ---------------------------------------------------------------------------
__device__ int g_cnt[NSPEC];
__device__ int g_or_odd;
__device__ int g_idx[NSPEC * NT];
__device__ __half g_x16[(size_t)NT * DIN];
__device__ __half g_H16[(size_t)NT * DHID];
__device__ __half g_w1[(size_t)NSPEC * DHID * DIN];   // [s][n][k] fp16
__device__ __half g_w2[(size_t)NSPEC * DOUT * DHID];

// ---------------------------------------------------------------------------
// Helpers
// ---------------------------------------------------------------------------
__device__ __forceinline__ uint32_t s2u(const void* p) {
    uint32_t a;
    asm("{ .reg .u64 t; cvta.to.shared.u64 t, %1; cvt.u32.u64 %0, t; }" : "=r"(a) : "l"(p));
    return a;
}
__device__ __forceinline__ uint32_t swz(uint32_t o) { return o ^ ((o >> 3) & 0x70u); }

#define CP_COMMIT() asm volatile("cp.async.commit_group;" ::: "memory")
template<int N> __device__ __forceinline__ void cp_wait() {
    asm volatile("cp.async.wait_group %0;" :: "n"(N) : "memory");
}
__device__ __forceinline__ void cp16z(uint32_t dst, const void* src, unsigned sz) {
    asm volatile("cp.async.cg.shared.global [%0], [%1], 16, %2;"
                 :: "r"(dst), "l"(src), "r"(sz) : "memory");
}

#define LDM4(r, a) \
    asm volatile("ldmatrix.sync.aligned.m8n8.x4.shared.b16 {%0,%1,%2,%3}, [%4];" \
                 : "=r"((r)[0]), "=r"((r)[1]), "=r"((r)[2]), "=r"((r)[3]) : "r"(a))

#define MMA(c, a, b) \
    asm volatile("mma.sync.aligned.m16n8k16.row.col.f32.f16.f16.f32 " \
                 "{%0,%1,%2,%3},{%4,%5,%6,%7},{%8,%9},{%0,%1,%2,%3};" \
                 : "+f"((c)[0]), "+f"((c)[1]), "+f"((c)[2]), "+f"((c)[3]) \
                 : "r"((a)[0]), "r"((a)[1]), "r"((a)[2]), "r"((a)[3]), \
                   "r"((b)[0]), "r"((b)[1]))

// ---------------------------------------------------------------------------
// conv_x: fp32 -> fp16. 16 floats/thread as 4 INDEPENDENT float4 loads
// (MLP=4 hides DRAM latency); grid 4096 instead of 16384.
// ---------------------------------------------------------------------------
__global__ void conv_x(const float* __restrict__ x) {
    size_t base = ((size_t)blockIdx.x * 256 + threadIdx.x) * 4;
    const size_t stride = (size_t)4096 * 256 * 4;     // one pass per j
    float4 v[4];
#pragma unroll
    for (int j = 0; j < 4; j++)
        v[j] = *(const float4*)(x + base + j * stride);
#pragma unroll
    for (int j = 0; j < 4; j++) {
        uint2 p;
        p.x = (uint32_t)__half_as_ushort(__float2half_rn(v[j].x))
            | ((uint32_t)__half_as_ushort(__float2half_rn(v[j].y)) << 16);
        p.y = (uint32_t)__half_as_ushort(__float2half_rn(v[j].z))
            | ((uint32_t)__half_as_ushort(__float2half_rn(v[j].w)) << 16);
        ((uint2*)g_x16)[(base + j * stride) / 4] = p;
    }
}

// ---------------------------------------------------------------------------
// Probe + counter reset (single block). Species dtype is ambiguous (JAX
// x64-off silently emits int32): int64 with values 0..3 has every odd 32-bit
// word zero; random int32 0..3 fails w.p. 1 - 4^-2048.
// ---------------------------------------------------------------------------
__global__ void k_probe(const int* __restrict__ w) {
    __shared__ int red[8];
    if (threadIdx.x < NSPEC) g_cnt[threadIdx.x] = 0;
    int v = 0;
#pragma unroll
    for (int j = 0; j < 8; j++)
        v |= w[2 * (threadIdx.x + j * 256) + 1];
    for (int o = 16; o > 0; o >>= 1) v |= __shfl_xor_sync(0xffffffffu, v, o);
    if ((threadIdx.x & 31) == 0) red[threadIdx.x >> 5] = v;
    __syncthreads();
    if (threadIdx.x == 0) {
        int r = 0;
#pragma unroll
        for (int j = 0; j < 8; j++) r |= red[j];
        g_or_odd = r;
    }
}

// ---------------------------------------------------------------------------
// Block-aggregated scatter: warp ballots -> per-warp smem histogram ->
// warp-scan -> 4 global atomics per block (256 total).
// ---------------------------------------------------------------------------
__global__ void __launch_bounds__(1024) k_scatter(const int* __restrict__ w) {
    __shared__ int wcnt[32][NSPEC];
    __shared__ int sbase[NSPEC];
    const int tid = threadIdx.x, wid = tid >> 5, lane = tid & 31;
    const int i = blockIdx.x * 1024 + tid;
    bool is64 = (g_or_odd == 0);
    int s = is64 ? w[2 * i] : w[i];
    int rank = 0;
#pragma unroll
    for (int t = 0; t < NSPEC; t++) {
        unsigned m = __ballot_sync(0xffffffffu, s == t);
        if (lane == 0) wcnt[wid][t] = __popc(m);
        if (s == t) rank = __popc(m & ((1u << lane) - 1u));
    }
    __syncthreads();
    if (wid < NSPEC) {                 // warp `wid` scans species `wid`
        int c = wcnt[lane][wid];
        int incl = c;
#pragma unroll
        for (int o = 1; o < 32; o <<= 1) {
            int n = __shfl_up_sync(0xffffffffu, incl, o);
            if (lane >= o) incl += n;
        }
        wcnt[lane][wid] = incl - c;    // exclusive prefix
        if (lane == 31) sbase[wid] = atomicAdd(&g_cnt[wid], incl);
    }
    __syncthreads();
    if ((unsigned)s < NSPEC)
        g_idx[s * NT + sbase[s] + wcnt[wid][s] + rank] = i;
}

// ---------------------------------------------------------------------------
// Merged weight transpose+convert: W1 blocks [0,1024), W2 blocks [1024,2048)
// ---------------------------------------------------------------------------
__global__ void conv_w_all(const float* __restrict__ W1, const float* __restrict__ W2) {
    __shared__ float sm[32][33];
    int id = blockIdx.x;
    const float* W; __half* T; int KD, ND, k0, n0, s;
    if (id < 1024) {
        W = W1; T = g_w1; KD = DIN; ND = DHID;
        k0 = (id & 7) * 32; n0 = ((id >> 3) & 31) * 32; s = id >> 8;
    } else {
        int j = id - 1024;
        W = W2; T = g_w2; KD = DHID; ND = DOUT;
        k0 = (j & 31) * 32; n0 = ((j >> 5) & 7) * 32; s = j >> 8;
    }
    int tx = threadIdx.x, ty = threadIdx.y;   // (32, 8)
    const float* Wp = W + (size_t)s * KD * ND;
#pragma unroll
    for (int j = 0; j < 4; j++)
        sm[ty + j * 8][tx] = Wp[(size_t)(k0 + ty + j * 8) * ND + n0 + tx];
    __syncthreads();
#pragma unroll
    for (int j = 0; j < 4; j++) {
        int n = ty + j * 8;
        T[((size_t)s * ND + n0 + n) * KD + k0 + tx] = __float2half_rn(sm[tx][n]);
    }
}

// ---------------------------------------------------------------------------
// mma.sync fp16 GEMM over one species bucket (proven round-11/13 core).
//   Block 128x128, K chunks of 64. 8 warps: warp tile 64x32.
//   3-stage cp.async pipeline, one __syncthreads per chunk, occupancy 2.
// Dynamic SMEM: 3 stages x 32KB (A 16K | B 16K), SW128-swizzled 128B rows.
// ---------------------------------------------------------------------------
#define GEMM_SMEM 98304

template<int KT, int NDIM, bool GATHER_A, bool SCATTER_OUT, bool DO_SILU>
__global__ void __launch_bounds__(256, 2)
moe_gemm(const __half* __restrict__ A, const __half* __restrict__ B,
         const float* __restrict__ bias,
         __half* __restrict__ O16, float* __restrict__ Of)
{
    constexpr int NC = KT / 64;
    extern __shared__ char dyn[];
    __shared__ int   tok[128];
    __shared__ float bsm[128];

    const int tid = threadIdx.x, wid = tid >> 5, lane = tid & 31;
    const int s   = blockIdx.z;
    const int cnt = g_cnt[s];
    const int m0  = blockIdx.x * 128;
    if (m0 >= cnt) return;
    const int n0    = blockIdx.y * 128;
    const int valid = min(128, cnt - m0);
    int off = 0;
#pragma unroll
    for (int t = 0; t < NSPEC; t++) if (t < s) off += g_cnt[t];
    const uint32_t sbase = s2u(dyn);

    for (int i = tid; i < 128; i += 256)
        tok[i] = (i < valid) ? g_idx[s * NT + m0 + i] : -1;
    if (tid < 128) bsm[tid] = bias[(size_t)s * NDIM + n0 + tid];
    __syncthreads();

    auto issue = [&](int c) {
        const int k0 = c * 64;
        const uint32_t bb = sbase + (uint32_t)(c % 3) * 32768u;
#pragma unroll
        for (int i = 0; i < 4; i++) {          // A: 128 rows x 8 units
            int t = tid + i * 256;
            int row = t >> 3, u = t & 7;
            int gr;
            if (GATHER_A) gr = tok[row];
            else          gr = (row < valid) ? (off + m0 + row) : -1;
            const __half* src = A + (size_t)max(gr, 0) * KT + k0 + u * 8;
            cp16z(bb + swz((uint32_t)row * 128u + u * 16u), src, (gr >= 0) ? 16u : 0u);
        }
#pragma unroll
        for (int i = 0; i < 4; i++) {          // B: 128 rows x 8 units
            int t = tid + i * 256;
            int row = t >> 3, u = t & 7;
            const __half* src = B + ((size_t)s * NDIM + n0 + row) * KT + k0 + u * 8;
            cp16z(bb + 16384u + swz((uint32_t)row * 128u + u * 16u), src, 16u);
        }
        CP_COMMIT();
    };

    float acc[4][4][4];
#pragma unroll
    for (int a = 0; a < 4; a++)
#pragma unroll
        for (int b = 0; b < 4; b++)
#pragma unroll
            for (int q = 0; q < 4; q++) acc[a][b][q] = 0.f;

    const int wm = wid & 1;
    const int wn = wid >> 1;
    const int ra = (lane & 7) + ((lane >> 3) & 1) * 8;
    const int ca = ((lane >> 4) & 1) * 8;
    const int rb = (lane & 7) + ((lane >> 4) & 1) * 8;
    const int cb = ((lane >> 3) & 1) * 8;

    issue(0);
    if (NC > 1) issue(1);
#pragma unroll 1
    for (int c = 0; c < NC; c++) {
        if (c + 1 < NC) cp_wait<1>();
        else            cp_wait<0>();
        __syncthreads();
        if (c + 2 < NC) issue(c + 2);
        const uint32_t bb = sbase + (uint32_t)(c % 3) * 32768u;
#pragma unroll
        for (int ks = 0; ks < 4; ks++) {
            uint32_t af[4][4], bf[2][4];
#pragma unroll
            for (int mt = 0; mt < 4; mt++) {
                uint32_t o = (uint32_t)((wm * 64 + mt * 16 + ra) * 128
                                        + (ks * 16 + ca) * 2);
                LDM4(af[mt], bb + swz(o));
            }
#pragma unroll
            for (int np = 0; np < 2; np++) {
                uint32_t o = (uint32_t)((wn * 32 + np * 16 + rb) * 128
                                        + (ks * 16 + cb) * 2);
                LDM4(bf[np], bb + 16384u + swz(o));
            }
#pragma unroll
            for (int mt = 0; mt < 4; mt++)
#pragma unroll
                for (int nt = 0; nt < 4; nt++)
                    MMA(acc[mt][nt], af[mt], &bf[nt >> 1][(nt & 1) * 2]);
        }
    }

    const int gid = lane >> 2, tig = lane & 3;
#pragma unroll
    for (int mt = 0; mt < 4; mt++)
#pragma unroll
        for (int half = 0; half < 2; half++) {
            int lrow = wm * 64 + mt * 16 + gid + half * 8;
            if (lrow >= valid) continue;
            int orow = SCATTER_OUT ? tok[lrow] : (off + m0 + lrow);
#pragma unroll
            for (int nt = 0; nt < 4; nt++) {
                int col = wn * 32 + nt * 8 + tig * 2;
                float v0 = acc[mt][nt][half * 2 + 0] + bsm[col];
                float v1 = acc[mt][nt][half * 2 + 1] + bsm[col + 1];
                if (DO_SILU) {
                    v0 = v0 / (1.f + __expf(-v0));
                    v1 = v1 / (1.f + __expf(-v1));
                    uint32_t p = (uint32_t)__half_as_ushort(__float2half_rn(v0))
                               | ((uint32_t)__half_as_ushort(__float2half_rn(v1)) << 16);
                    *(uint32_t*)(O16 + (size_t)orow * NDIM + n0 + col) = p;
                } else {
                    float2 v = make_float2(v0, v1);
                    *(float2*)(Of + (size_t)orow * NDIM + n0 + col) = v;
                }
            }
        }
}

// ---------------------------------------------------------------------------
// Launch (round-13 proven topology). Pre-phase forked 3 ways:
// conv_x (main) || conv_w (s1) || probe+scatter (s2); join; GEMM1; GEMM2.
// ---------------------------------------------------------------------------
extern "C" void kernel_launch(void* const* d_in, const int* in_sizes, int n_in,
                              void* d_out, int out_size)
{
    const float* x   = (const float*)d_in[0];
    const int*   spw = (const int*)d_in[1];
    const float* W1  = (const float*)d_in[2];
    const float* b1  = (const float*)d_in[3];
    const float* W2  = (const float*)d_in[4];
    const float* b2  = (const float*)d_in[5];
    float*       out = (float*)d_out;

    __half *x16, *H16, *w1, *w2;
    cudaGetSymbolAddress((void**)&x16, g_x16);
    cudaGetSymbolAddress((void**)&H16, g_H16);
    cudaGetSymbolAddress((void**)&w1,  g_w1);
    cudaGetSymbolAddress((void**)&w2,  g_w2);

    static cudaStream_t s1 = nullptr, s2 = nullptr;
    static cudaEvent_t  evF = nullptr, evJ1 = nullptr, evJ2 = nullptr;
    if (!s1) {
        cudaStreamCreateWithFlags(&s1, cudaStreamNonBlocking);
        cudaStreamCreateWithFlags(&s2, cudaStreamNonBlocking);
        cudaEventCreateWithFlags(&evF,  cudaEventDisableTiming);
        cudaEventCreateWithFlags(&evJ1, cudaEventDisableTiming);
        cudaEventCreateWithFlags(&evJ2, cudaEventDisableTiming);
        cudaFuncSetAttribute(moe_gemm<DIN,  DHID, true,  false, true>,
                             cudaFuncAttributeMaxDynamicSharedMemorySize, GEMM_SMEM);
        cudaFuncSetAttribute(moe_gemm<DHID, DOUT, false, true,  false>,
                             cudaFuncAttributeMaxDynamicSharedMemorySize, GEMM_SMEM);
    }

    // Fork independent pre-phase chains.
    cudaEventRecord(evF, 0);
    cudaStreamWaitEvent(s1, evF, 0);
    cudaStreamWaitEvent(s2, evF, 0);

    conv_w_all<<<2048, dim3(32, 8), 0, s1>>>(W1, W2);
    cudaEventRecord(evJ1, s1);

    k_probe  <<<1, 256, 0, s2>>>(spw);     // + counter resets
    k_scatter<<<64, 1024, 0, s2>>>(spw);
    cudaEventRecord(evJ2, s2);

    conv_x<<<4096, 256>>>(x);              // main stream, MLP=4 version

    // Join: GEMM1 needs x16 (main), w1 (s1), buckets (s2).
    cudaStreamWaitEvent(0, evJ1, 0);
    cudaStreamWaitEvent(0, evJ2, 0);

    // GEMM1: H = silu(x @ W1[s] + b1[s]) -> compact fp16
    moe_gemm<DIN, DHID, true, false, true>
        <<<dim3(MT, DHID / 128, NSPEC), 256, GEMM_SMEM>>>(
            x16, w1, b1, H16, nullptr);

    // GEMM2: out = H @ W2[s] + b2[s] -> scatter fp32 by token
    moe_gemm<DHID, DOUT, false, true, false>
        <<<dim3(MT, DOUT / 128, NSPEC), 256, GEMM_SMEM>>>(
            H16, w2, b2, nullptr, out);
}